// round 9
// baseline (speedup 1.0000x reference)
#include <cuda_runtime.h>
#include <cuda_bf16.h>
#include <cstdint>
#include <math.h>

#define DIM   768
#define HEADS 12
#define HD    64
#define BS    32
#define NMM   256
#define NV    196
#define NA    60
#define NSRC  256            // NV + NA
#define MQ    (BS * NMM)     // 8192

// ---------------------------------------------------------------------------
// Scratch (static __device__ globals; allocation is forbidden)
// ---------------------------------------------------------------------------
__device__ float g_attn_fallback[(size_t)BS * HEADS * NMM * NSRC];

__device__ __nv_bfloat16 g_Axmm_hi[(size_t)MQ * DIM];
__device__ __nv_bfloat16 g_Axmm_lo[(size_t)MQ * DIM];
__device__ __nv_bfloat16 g_Asrc_hi[(size_t)MQ * DIM];
__device__ __nv_bfloat16 g_Asrc_lo[(size_t)MQ * DIM];
__device__ __nv_bfloat16 g_Qh [(size_t)MQ * DIM];
__device__ __nv_bfloat16 g_Ql [(size_t)MQ * DIM];
__device__ __nv_bfloat16 g_KVh[(size_t)MQ * 2 * DIM];
__device__ __nv_bfloat16 g_KVl[(size_t)MQ * 2 * DIM];
__device__ __nv_bfloat16 g_Oh [(size_t)MQ * DIM];
__device__ __nv_bfloat16 g_Ol [(size_t)MQ * DIM];
__device__ __nv_bfloat16 g_Wqt_hi [(size_t)DIM * DIM];
__device__ __nv_bfloat16 g_Wqt_lo [(size_t)DIM * DIM];
__device__ __nv_bfloat16 g_Wkvt_hi[(size_t)2 * DIM * DIM];
__device__ __nv_bfloat16 g_Wkvt_lo[(size_t)2 * DIM * DIM];
__device__ __nv_bfloat16 g_Wpt_hi [(size_t)DIM * DIM];
__device__ __nv_bfloat16 g_Wpt_lo [(size_t)DIM * DIM];

// ---------------------------------------------------------------------------
// helpers
// ---------------------------------------------------------------------------
__device__ __forceinline__ uint32_t smem_u32(const void* p) {
    uint32_t a;
    asm("{ .reg .u64 t; cvta.to.shared.u64 t, %1; cvt.u32.u64 %0, t; }" : "=r"(a) : "l"(p));
    return a;
}
__device__ __forceinline__ uint32_t pack_bf2(__nv_bfloat16 a, __nv_bfloat16 b) {
    __nv_bfloat162 t = __halves2bfloat162(a, b);
    return *reinterpret_cast<uint32_t*>(&t);
}
__device__ __forceinline__ void split2(float a, float b, uint32_t& hi, uint32_t& lo) {
    __nv_bfloat16 ha = __float2bfloat16(a), hb = __float2bfloat16(b);
    hi = pack_bf2(ha, hb);
    lo = pack_bf2(__float2bfloat16(a - __bfloat162float(ha)),
                  __float2bfloat16(b - __bfloat162float(hb)));
}
__device__ __forceinline__ void cp_async16(uint32_t saddr, const void* gptr) {
    asm volatile("cp.async.cg.shared.global [%0], [%1], 16;" :: "r"(saddr), "l"(gptr));
}
__device__ __forceinline__ void cp_commit() { asm volatile("cp.async.commit_group;"); }
template<int N_>
__device__ __forceinline__ void cp_wait() { asm volatile("cp.async.wait_group %0;" :: "n"(N_)); }

__device__ __forceinline__ void mma16816(float* c, uint32_t a0, uint32_t a1,
                                         uint32_t a2, uint32_t a3,
                                         uint32_t b0, uint32_t b1) {
    asm volatile(
        "mma.sync.aligned.m16n8k16.row.col.f32.bf16.bf16.f32 "
        "{%0,%1,%2,%3}, {%4,%5,%6,%7}, {%8,%9}, {%0,%1,%2,%3};"
        : "+f"(c[0]), "+f"(c[1]), "+f"(c[2]), "+f"(c[3])
        : "r"(a0), "r"(a1), "r"(a2), "r"(a3), "r"(b0), "r"(b1));
}
__device__ __forceinline__ void ldmx4(uint32_t* r, uint32_t saddr) {
    asm volatile("ldmatrix.sync.aligned.m8n8.x4.shared.b16 {%0,%1,%2,%3}, [%4];"
                 : "=r"(r[0]), "=r"(r[1]), "=r"(r[2]), "=r"(r[3]) : "r"(saddr));
}
__device__ __forceinline__ void ldmx4t(uint32_t* r, uint32_t saddr) {
    asm volatile("ldmatrix.sync.aligned.m8n8.x4.trans.shared.b16 {%0,%1,%2,%3}, [%4];"
                 : "=r"(r[0]), "=r"(r[1]), "=r"(r[2]), "=r"(r[3]) : "r"(saddr));
}
__device__ __forceinline__ void st_cs_f2(float* p, float x, float y) {
    asm volatile("st.global.cs.v2.f32 [%0], {%1, %2};" :: "l"(p), "f"(x), "f"(y) : "memory");
}
__device__ __forceinline__ void split4(float4 x, uint2& hi, uint2& lo) {
    uint32_t h0, l0, h1, l1;
    split2(x.x, x.y, h0, l0);
    split2(x.z, x.w, h1, l1);
    hi = make_uint2(h0, h1);
    lo = make_uint2(l0, l1);
}

// ---------------------------------------------------------------------------
// Conversion kernels: fp32 -> (hi, lo) bf16 split (vectorized x4)
// ---------------------------------------------------------------------------
__global__ void split_plain_v4(const float4* __restrict__ X,
                               uint2* __restrict__ hi, uint2* __restrict__ lo,
                               size_t n4) {
    for (size_t i = (size_t)blockIdx.x * blockDim.x + threadIdx.x; i < n4;
         i += (size_t)gridDim.x * blockDim.x) {
        uint2 H, L;
        split4(X[i], H, L);
        hi[i] = H;
        lo[i] = L;
    }
}

__global__ void split_concat_v4(const float4* __restrict__ xv, const float4* __restrict__ xa,
                                uint2* __restrict__ hi, uint2* __restrict__ lo) {
    const int D4 = DIM / 4;
    size_t n4 = (size_t)MQ * D4;
    for (size_t i = (size_t)blockIdx.x * blockDim.x + threadIdx.x; i < n4;
         i += (size_t)gridDim.x * blockDim.x) {
        size_t row = i / D4, cg = i % D4;
        int b = (int)(row >> 8), t = (int)(row & 255);
        float4 x = (t < NV) ? xv[((size_t)b * NV + t) * D4 + cg]
                            : xa[((size_t)b * NA + (t - NV)) * D4 + cg];
        uint2 H, L;
        split4(x, H, L);
        hi[i] = H;
        lo[i] = L;
    }
}

// W [K][N] fp32 -> Wt [N][K] bf16 hi/lo
__global__ void transpose_split(const float* __restrict__ W,
                                __nv_bfloat16* __restrict__ Thi,
                                __nv_bfloat16* __restrict__ Tlo, int K, int N) {
    __shared__ float tile[32][33];
    int n0 = blockIdx.x * 32, k0 = blockIdx.y * 32;
    int tx = threadIdx.x, ty = threadIdx.y;     // (32, 8)
#pragma unroll
    for (int j = 0; j < 32; j += 8)
        tile[ty + j][tx] = W[(size_t)(k0 + ty + j) * N + (n0 + tx)];
    __syncthreads();
#pragma unroll
    for (int j = 0; j < 32; j += 8) {
        float v = tile[tx][ty + j];
        __nv_bfloat16 h = __float2bfloat16(v);
        size_t o = (size_t)(n0 + ty + j) * K + (k0 + tx);
        Thi[o] = h;
        Tlo[o] = __float2bfloat16(v - __bfloat162float(h));
    }
}

// ---------------------------------------------------------------------------
// HMMA split-bf16 GEMM body: C[128x128 tile] = A[M,K] @ Bt[N,K]^T
// CTA 128x128, 8 warps 64x32, K-chunk 32, double buffer, ldmatrix frags.
// ---------------------------------------------------------------------------
#define CK       32
#define SROW     40
#define TILE_BF  (128 * SROW)
#define ST_ELEMS (4 * TILE_BF)
#define GEMM_SMEM (2 * ST_ELEMS * 2)        // 81920 bytes

template<bool SPLIT>
__device__ __forceinline__ void gemm_body(
    const __nv_bfloat16* __restrict__ Ahi, const __nv_bfloat16* __restrict__ Alo,
    const __nv_bfloat16* __restrict__ Bhi, const __nv_bfloat16* __restrict__ Blo,
    float* __restrict__ C, __nv_bfloat16* __restrict__ Chi, __nv_bfloat16* __restrict__ Clo,
    int m0, int n0, int N, int K, const float* __restrict__ bias,
    __nv_bfloat16* sm)
{
    const int tid  = threadIdx.x;
    const int wid  = tid >> 5;
    const int lane = tid & 31;
    const int wm   = (wid >> 2) * 64;
    const int wn   = (wid & 3) * 32;
    const int NC   = K / CK;                 // 24

    const int lr = lane >> 2;
    const int lc = (lane & 3) * 2;

    const int arow = (lane & 7) + ((lane >> 3) & 1) * 8;
    const int akof = (lane >> 4) * 8;
    const int brow = (lane & 7) + ((lane >> 4) << 3);
    const int bkof = ((lane >> 3) & 1) * 8;

    float acc[4][4][4];
#pragma unroll
    for (int i = 0; i < 4; i++)
#pragma unroll
        for (int j = 0; j < 4; j++)
#pragma unroll
            for (int v = 0; v < 4; v++) acc[i][j][v] = 0.f;

    uint32_t smb = smem_u32(sm);
    const uint32_t offAh = (uint32_t)(0 * TILE_BF + (wm + arow) * SROW + akof) * 2;
    const uint32_t offAl = (uint32_t)(1 * TILE_BF + (wm + arow) * SROW + akof) * 2;
    const uint32_t offBh = (uint32_t)(2 * TILE_BF + (wn + brow) * SROW + bkof) * 2;
    const uint32_t offBl = (uint32_t)(3 * TILE_BF + (wn + brow) * SROW + bkof) * 2;

    auto load_chunk = [&](int c, int s) {
        uint32_t base = smb + (uint32_t)s * ST_ELEMS * 2;
        int k0 = c * CK;
#pragma unroll
        for (int it = 0; it < 2; it++) {
            int e   = tid + it * 256;
            int r   = e >> 2, seg = e & 3;
            uint32_t doff = (uint32_t)(r * SROW + seg * 8) * 2;
            size_t  goffA = (size_t)(m0 + r) * K + k0 + seg * 8;
            size_t  goffB = (size_t)(n0 + r) * K + k0 + seg * 8;
            cp_async16(base + 0 * TILE_BF * 2 + doff, Ahi + goffA);
            cp_async16(base + 1 * TILE_BF * 2 + doff, Alo + goffA);
            cp_async16(base + 2 * TILE_BF * 2 + doff, Bhi + goffB);
            cp_async16(base + 3 * TILE_BF * 2 + doff, Blo + goffB);
        }
        cp_commit();
    };

    load_chunk(0, 0);

    for (int c = 0; c < NC; c++) {
        int s = c & 1;
        if (c + 1 < NC) load_chunk(c + 1, (c + 1) & 1);
        if (c + 1 < NC) cp_wait<1>(); else cp_wait<0>();
        __syncthreads();

        uint32_t stg = smb + (uint32_t)s * ST_ELEMS * 2;

#pragma unroll
        for (int ks = 0; ks < 2; ks++) {
            uint32_t kbb = (uint32_t)(ks * 16) * 2;
            uint32_t bh[4][2], bl[4][2];
#pragma unroll
            for (int p = 0; p < 2; p++) {
                uint32_t t4[4];
                ldmx4(t4, stg + offBh + kbb + (uint32_t)(p * 16 * SROW) * 2);
                bh[2 * p][0] = t4[0]; bh[2 * p][1] = t4[1];
                bh[2 * p + 1][0] = t4[2]; bh[2 * p + 1][1] = t4[3];
                ldmx4(t4, stg + offBl + kbb + (uint32_t)(p * 16 * SROW) * 2);
                bl[2 * p][0] = t4[0]; bl[2 * p][1] = t4[1];
                bl[2 * p + 1][0] = t4[2]; bl[2 * p + 1][1] = t4[3];
            }
#pragma unroll
            for (int mt = 0; mt < 4; mt++) {
                uint32_t ah[4], al[4];
                ldmx4(ah, stg + offAh + kbb + (uint32_t)(mt * 16 * SROW) * 2);
                ldmx4(al, stg + offAl + kbb + (uint32_t)(mt * 16 * SROW) * 2);
#pragma unroll
                for (int nt = 0; nt < 4; nt++) {
                    mma16816(acc[mt][nt], ah[0], ah[1], ah[2], ah[3], bh[nt][0], bh[nt][1]);
                    mma16816(acc[mt][nt], ah[0], ah[1], ah[2], ah[3], bl[nt][0], bl[nt][1]);
                    mma16816(acc[mt][nt], al[0], al[1], al[2], al[3], bh[nt][0], bh[nt][1]);
                }
            }
        }
        __syncthreads();
    }

#pragma unroll
    for (int mt = 0; mt < 4; mt++) {
        int r0 = m0 + wm + mt * 16 + lr;
#pragma unroll
        for (int nt = 0; nt < 4; nt++) {
            int cc = n0 + wn + nt * 8 + lc;
            if (SPLIT) {
                uint32_t h0, l0, h1, l1;
                split2(acc[mt][nt][0], acc[mt][nt][1], h0, l0);
                split2(acc[mt][nt][2], acc[mt][nt][3], h1, l1);
                *(uint32_t*)(Chi + (size_t)r0 * N + cc)       = h0;
                *(uint32_t*)(Clo + (size_t)r0 * N + cc)       = l0;
                *(uint32_t*)(Chi + (size_t)(r0 + 8) * N + cc) = h1;
                *(uint32_t*)(Clo + (size_t)(r0 + 8) * N + cc) = l1;
            } else {
                float b0 = bias ? bias[cc]     : 0.f;
                float b1 = bias ? bias[cc + 1] : 0.f;
                float* p0 = C + (size_t)r0 * N + cc;
                float* p1 = C + (size_t)(r0 + 8) * N + cc;
                p0[0] = acc[mt][nt][0] + b0;
                p0[1] = acc[mt][nt][1] + b1;
                p1[0] = acc[mt][nt][2] + b0;
                p1[1] = acc[mt][nt][3] + b1;
            }
        }
    }
}

// Fused Q + KV projection GEMM. grid = (6 + 12, 64).
__global__ void __launch_bounds__(256, 2) gemm_qkv(
    const __nv_bfloat16* __restrict__ Axh, const __nv_bfloat16* __restrict__ Axl,
    const __nv_bfloat16* __restrict__ Wqh, const __nv_bfloat16* __restrict__ Wql,
    __nv_bfloat16* __restrict__ Qh, __nv_bfloat16* __restrict__ Ql,
    const __nv_bfloat16* __restrict__ Ash, const __nv_bfloat16* __restrict__ Asl,
    const __nv_bfloat16* __restrict__ Wkh, const __nv_bfloat16* __restrict__ Wkl,
    __nv_bfloat16* __restrict__ KVh, __nv_bfloat16* __restrict__ KVl)
{
    extern __shared__ __align__(16) __nv_bfloat16 sm[];
    int bx = blockIdx.x, m0 = blockIdx.y * 128;
    if (bx < DIM / 128) {
        gemm_body<true>(Axh, Axl, Wqh, Wql, nullptr, Qh, Ql,
                        m0, bx * 128, DIM, DIM, nullptr, sm);
    } else {
        gemm_body<true>(Ash, Asl, Wkh, Wkl, nullptr, KVh, KVl,
                        m0, (bx - DIM / 128) * 128, 2 * DIM, DIM, nullptr, sm);
    }
}

// Output projection GEMM (fp32 + bias).
__global__ void __launch_bounds__(256, 2) gemm_proj(
    const __nv_bfloat16* __restrict__ Ahi, const __nv_bfloat16* __restrict__ Alo,
    const __nv_bfloat16* __restrict__ Bhi, const __nv_bfloat16* __restrict__ Blo,
    float* __restrict__ C, const float* __restrict__ bias)
{
    extern __shared__ __align__(16) __nv_bfloat16 sm[];
    gemm_body<false>(Ahi, Alo, Bhi, Blo, C, nullptr, nullptr,
                     blockIdx.y * 128, blockIdx.x * 128, DIM, DIM, bias, sm);
}

// ---------------------------------------------------------------------------
// HMMA flash-style attention. CTA = (q-tile 128, h, b), 256 thr (8 warps).
// Warp owns 16 q-rows x 256 keys. 3-term split everywhere. ldmatrix frags.
// ---------------------------------------------------------------------------
#define QSTR 72
#define AT_QH 0
#define AT_QL (128 * QSTR)
#define AT_KH (2 * 128 * QSTR)
#define AT_KL (AT_KH + 256 * QSTR)
#define AT_VH (AT_KH + 2 * 256 * QSTR)
#define AT_VL (AT_KH + 3 * 256 * QSTR)
#define AT_SMEM_ELE (AT_KH + 4 * 256 * QSTR)      // 92160 bf16
#define AT_SMEM_BYTES (AT_SMEM_ELE * 2)           // 184320

__global__ void __launch_bounds__(256) attn_mma(
    const __nv_bfloat16* __restrict__ Qhi, const __nv_bfloat16* __restrict__ Qlo,
    const __nv_bfloat16* __restrict__ KVhi, const __nv_bfloat16* __restrict__ KVlo,
    float* __restrict__ attn,
    __nv_bfloat16* __restrict__ Ohi, __nv_bfloat16* __restrict__ Olo)
{
    extern __shared__ __align__(16) __nv_bfloat16 asm_[];
    const int tid  = threadIdx.x;
    const int wid  = tid >> 5;
    const int lane = tid & 31;
    const int lr   = lane >> 2;
    const int lc   = lane & 3;
    const int b    = blockIdx.z;
    const int h    = blockIdx.y;
    const int q0   = blockIdx.x * 128;

    const int arow = (lane & 7) + ((lane >> 3) & 1) * 8;
    const int akof = (lane >> 4) * 8;
    const int brow = (lane & 7) + ((lane >> 4) << 3);
    const int bkof = ((lane >> 3) & 1) * 8;

    // ---- load tiles ----
    {
        const __nv_bfloat16* Qgh = Qhi + ((size_t)(b * NMM + q0)) * DIM + h * HD;
        const __nv_bfloat16* Qgl = Qlo + ((size_t)(b * NMM + q0)) * DIM + h * HD;
#pragma unroll
        for (int it = 0; it < 4; it++) {
            int e = tid + it * 256;
            int r = e >> 3, s = e & 7;
            *(uint4*)&asm_[AT_QH + r * QSTR + s * 8] = *(const uint4*)(Qgh + (size_t)r * DIM + s * 8);
            *(uint4*)&asm_[AT_QL + r * QSTR + s * 8] = *(const uint4*)(Qgl + (size_t)r * DIM + s * 8);
        }
        const __nv_bfloat16* Kgh = KVhi + ((size_t)b * NSRC) * (2 * DIM) + h * HD;
        const __nv_bfloat16* Kgl = KVlo + ((size_t)b * NSRC) * (2 * DIM) + h * HD;
#pragma unroll
        for (int it = 0; it < 8; it++) {
            int e = tid + it * 256;
            int r = e >> 3, s = e & 7;
            size_t go = (size_t)r * (2 * DIM) + s * 8;
            *(uint4*)&asm_[AT_KH + r * QSTR + s * 8] = *(const uint4*)(Kgh + go);
            *(uint4*)&asm_[AT_KL + r * QSTR + s * 8] = *(const uint4*)(Kgl + go);
            *(uint4*)&asm_[AT_VH + r * QSTR + s * 8] = *(const uint4*)(Kgh + go + DIM);
            *(uint4*)&asm_[AT_VL + r * QSTR + s * 8] = *(const uint4*)(Kgl + go + DIM);
        }
    }
    __syncthreads();

    uint32_t smb = smem_u32(asm_);

    // ---- Q fragments via ldmatrix.x4 ----
    uint32_t qh[4][4], ql[4][4];
    {
        uint32_t qoff = smb + (uint32_t)((wid * 16 + arow) * QSTR + akof) * 2;
#pragma unroll
        for (int kt = 0; kt < 4; kt++) {
            ldmx4(qh[kt], qoff + (uint32_t)(AT_QH * 2) + kt * 32);
            ldmx4(ql[kt], qoff + (uint32_t)(AT_QL * 2) + kt * 32);
        }
    }

    // ---- S = Q K^T (3-term split), kt-outer so consecutive MMAs are independent ----
    float acc[32][4];
#pragma unroll
    for (int t = 0; t < 32; t++)
#pragma unroll
        for (int v = 0; v < 4; v++) acc[t][v] = 0.f;

    {
        uint32_t kbase = smb + (uint32_t)(brow * QSTR + bkof) * 2;
#pragma unroll
        for (int kt = 0; kt < 4; kt++) {
#pragma unroll 4
            for (int p = 0; p < 16; p++) {
                uint32_t prow = kbase + (uint32_t)(p * 16 * QSTR) * 2;
                uint32_t kh4[4], kl4[4];
                ldmx4(kh4, prow + (uint32_t)(AT_KH * 2) + kt * 32);
                ldmx4(kl4, prow + (uint32_t)(AT_KL * 2) + kt * 32);
                mma16816(acc[2 * p],     qh[kt][0], qh[kt][1], qh[kt][2], qh[kt][3], kh4[0], kh4[1]);
                mma16816(acc[2 * p + 1], qh[kt][0], qh[kt][1], qh[kt][2], qh[kt][3], kh4[2], kh4[3]);
                mma16816(acc[2 * p],     qh[kt][0], qh[kt][1], qh[kt][2], qh[kt][3], kl4[0], kl4[1]);
                mma16816(acc[2 * p + 1], qh[kt][0], qh[kt][1], qh[kt][2], qh[kt][3], kl4[2], kl4[3]);
                mma16816(acc[2 * p],     ql[kt][0], ql[kt][1], ql[kt][2], ql[kt][3], kh4[0], kh4[1]);
                mma16816(acc[2 * p + 1], ql[kt][0], ql[kt][1], ql[kt][2], ql[kt][3], kh4[2], kh4[3]);
            }
        }
    }

    // ---- softmax (rows lr and lr+8 of this warp's 16) ----
    const float scale = 0.125f;
    float mx0 = -1e30f, mx1 = -1e30f;
#pragma unroll
    for (int t = 0; t < 32; t++) {
        mx0 = fmaxf(mx0, fmaxf(acc[t][0], acc[t][1]));
        mx1 = fmaxf(mx1, fmaxf(acc[t][2], acc[t][3]));
    }
    mx0 = fmaxf(mx0, __shfl_xor_sync(0xffffffffu, mx0, 1));
    mx0 = fmaxf(mx0, __shfl_xor_sync(0xffffffffu, mx0, 2));
    mx1 = fmaxf(mx1, __shfl_xor_sync(0xffffffffu, mx1, 1));
    mx1 = fmaxf(mx1, __shfl_xor_sync(0xffffffffu, mx1, 2));
    float s0 = 0.f, s1 = 0.f;
#pragma unroll
    for (int t = 0; t < 32; t++) {
        acc[t][0] = __expf((acc[t][0] - mx0) * scale); s0 += acc[t][0];
        acc[t][1] = __expf((acc[t][1] - mx0) * scale); s0 += acc[t][1];
        acc[t][2] = __expf((acc[t][2] - mx1) * scale); s1 += acc[t][2];
        acc[t][3] = __expf((acc[t][3] - mx1) * scale); s1 += acc[t][3];
    }
    s0 += __shfl_xor_sync(0xffffffffu, s0, 1);
    s0 += __shfl_xor_sync(0xffffffffu, s0, 2);
    s1 += __shfl_xor_sync(0xffffffffu, s1, 1);
    s1 += __shfl_xor_sync(0xffffffffu, s1, 2);
    float i0 = 1.f / s0, i1 = 1.f / s1;
#pragma unroll
    for (int t = 0; t < 32; t++) {
        acc[t][0] *= i0; acc[t][1] *= i0; acc[t][2] *= i1; acc[t][3] *= i1;
    }

    // ---- write attn probs (fp32, global, streaming) ----
    {
        float* ar0 = attn + ((size_t)((b * HEADS + h) * NMM) + q0 + wid * 16 + lr) * NSRC + 2 * lc;
        float* ar1 = ar0 + (size_t)8 * NSRC;
#pragma unroll
        for (int t = 0; t < 32; t++) {
            st_cs_f2(ar0 + t * 8, acc[t][0], acc[t][1]);
            st_cs_f2(ar1 + t * 8, acc[t][2], acc[t][3]);
        }
    }

    // ---- convert P to bf16 hi/lo A-fragments ----
    uint32_t ph[16][4], pl[16][4];
#pragma unroll
    for (int t = 0; t < 16; t++) {
        split2(acc[2 * t][0],     acc[2 * t][1],     ph[t][0], pl[t][0]);
        split2(acc[2 * t][2],     acc[2 * t][3],     ph[t][1], pl[t][1]);
        split2(acc[2 * t + 1][0], acc[2 * t + 1][1], ph[t][2], pl[t][2]);
        split2(acc[2 * t + 1][2], acc[2 * t + 1][3], ph[t][3], pl[t][3]);
    }

    // ---- O = P V (3-term split), V B-frags via ldmatrix.x4.trans ----
    float oacc[8][4];
#pragma unroll
    for (int nd = 0; nd < 8; nd++)
#pragma unroll
        for (int v = 0; v < 4; v++) oacc[nd][v] = 0.f;

    {
        uint32_t vbase = smb + (uint32_t)((lane & 15) * QSTR + (lane >> 4) * 8) * 2;
#pragma unroll
        for (int kt = 0; kt < 16; kt++) {
            uint32_t vrow = vbase + (uint32_t)(kt * 16 * QSTR) * 2;
#pragma unroll
            for (int ndp = 0; ndp < 4; ndp++) {
                uint32_t vh4[4], vl4[4];
                ldmx4t(vh4, vrow + (uint32_t)(AT_VH * 2) + ndp * 32);
                ldmx4t(vl4, vrow + (uint32_t)(AT_VL * 2) + ndp * 32);
                mma16816(oacc[2 * ndp],     ph[kt][0], ph[kt][1], ph[kt][2], ph[kt][3], vh4[0], vh4[1]);
                mma16816(oacc[2 * ndp + 1], ph[kt][0], ph[kt][1], ph[kt][2], ph[kt][3], vh4[2], vh4[3]);
                mma16816(oacc[2 * ndp],     ph[kt][0], ph[kt][1], ph[kt][2], ph[kt][3], vl4[0], vl4[1]);
                mma16816(oacc[2 * ndp + 1], ph[kt][0], ph[kt][1], ph[kt][2], ph[kt][3], vl4[2], vl4[3]);
                mma16816(oacc[2 * ndp],     pl[kt][0], pl[kt][1], pl[kt][2], pl[kt][3], vh4[0], vh4[1]);
                mma16816(oacc[2 * ndp + 1], pl[kt][0], pl[kt][1], pl[kt][2], pl[kt][3], vh4[2], vh4[3]);
            }
        }
    }

    // ---- write O as bf16 hi/lo ----
    {
        size_t row0 = (size_t)(b * NMM + q0 + wid * 16 + lr);
        __nv_bfloat16* oh0 = Ohi + row0 * DIM + h * HD + 2 * lc;
        __nv_bfloat16* ol0 = Olo + row0 * DIM + h * HD + 2 * lc;
        __nv_bfloat16* oh1 = oh0 + (size_t)8 * DIM;
        __nv_bfloat16* ol1 = ol0 + (size_t)8 * DIM;
#pragma unroll
        for (int nd = 0; nd < 8; nd++) {
            uint32_t hh, ll;
            split2(oacc[nd][0], oacc[nd][1], hh, ll);
            *(uint32_t*)(oh0 + nd * 8) = hh;
            *(uint32_t*)(ol0 + nd * 8) = ll;
            split2(oacc[nd][2], oacc[nd][3], hh, ll);
            *(uint32_t*)(oh1 + nd * 8) = hh;
            *(uint32_t*)(ol1 + nd * 8) = ll;
        }
    }
}

// ---------------------------------------------------------------------------
extern "C" void kernel_launch(void* const* d_in, const int* in_sizes, int n_in,
                              void* d_out, int out_size)
{
    const float* xmm   = (const float*)d_in[0];
    const float* xv    = (const float*)d_in[1];
    const float* xa    = (const float*)d_in[2];
    const float* Wq    = (const float*)d_in[3];
    const float* Wkv   = (const float*)d_in[4];
    const float* Wproj = (const float*)d_in[5];
    const float* bproj = (const float*)d_in[6];

    float* out = (float*)d_out;

    float* attn_fb;
    cudaGetSymbolAddress((void**)&attn_fb, g_attn_fallback);

    __nv_bfloat16 *Axh, *Axl, *Ash, *Asl;
    __nv_bfloat16 *Qh, *Ql, *KVh, *KVl, *Oh, *Ol;
    __nv_bfloat16 *Wqh, *Wql, *Wkh, *Wkl, *Wph, *Wpl;
    cudaGetSymbolAddress((void**)&Axh, g_Axmm_hi);
    cudaGetSymbolAddress((void**)&Axl, g_Axmm_lo);
    cudaGetSymbolAddress((void**)&Ash, g_Asrc_hi);
    cudaGetSymbolAddress((void**)&Asl, g_Asrc_lo);
    cudaGetSymbolAddress((void**)&Qh,  g_Qh);
    cudaGetSymbolAddress((void**)&Ql,  g_Ql);
    cudaGetSymbolAddress((void**)&KVh, g_KVh);
    cudaGetSymbolAddress((void**)&KVl, g_KVl);
    cudaGetSymbolAddress((void**)&Oh,  g_Oh);
    cudaGetSymbolAddress((void**)&Ol,  g_Ol);
    cudaGetSymbolAddress((void**)&Wqh, g_Wqt_hi);
    cudaGetSymbolAddress((void**)&Wql, g_Wqt_lo);
    cudaGetSymbolAddress((void**)&Wkh, g_Wkvt_hi);
    cudaGetSymbolAddress((void**)&Wkl, g_Wkvt_lo);
    cudaGetSymbolAddress((void**)&Wph, g_Wpt_hi);
    cudaGetSymbolAddress((void**)&Wpl, g_Wpt_lo);

    const size_t out_elems  = (size_t)MQ * DIM;
    const size_t attn_elems = (size_t)BS * HEADS * NMM * NSRC;
    float* attn_out = ((size_t)out_size >= out_elems + attn_elems)
                        ? out + out_elems : attn_fb;

    cudaFuncSetAttribute(gemm_qkv,  cudaFuncAttributeMaxDynamicSharedMemorySize, GEMM_SMEM);
    cudaFuncSetAttribute(gemm_proj, cudaFuncAttributeMaxDynamicSharedMemorySize, GEMM_SMEM);
    cudaFuncSetAttribute(attn_mma,  cudaFuncAttributeMaxDynamicSharedMemorySize, AT_SMEM_BYTES);

    // --- conversions ---
    {
        dim3 bb(32, 8);
        transpose_split<<<dim3(DIM / 32, DIM / 32), bb>>>(Wq, Wqh, Wql, DIM, DIM);
        transpose_split<<<dim3(2 * DIM / 32, DIM / 32), bb>>>(Wkv, Wkh, Wkl, DIM, 2 * DIM);
        transpose_split<<<dim3(DIM / 32, DIM / 32), bb>>>(Wproj, Wph, Wpl, DIM, DIM);
    }
    split_plain_v4<<<1024, 256>>>((const float4*)xmm, (uint2*)Axh, (uint2*)Axl,
                                  (size_t)MQ * DIM / 4);
    split_concat_v4<<<1024, 256>>>((const float4*)xv, (const float4*)xa,
                                   (uint2*)Ash, (uint2*)Asl);

    // --- fused Q + KV projection ---
    gemm_qkv<<<dim3(3 * DIM / 128, MQ / 128), 256, GEMM_SMEM>>>(
        Axh, Axl, Wqh, Wql, Qh, Ql,
        Ash, Asl, Wkh, Wkl, KVh, KVl);
    // --- attention ---
    attn_mma<<<dim3(NMM / 128, HEADS, BS), 256, AT_SMEM_BYTES>>>(
        Qh, Ql, KVh, KVl, attn_out, Oh, Ol);
    // --- out = O @ Wproj + bproj (fp32) ---
    gemm_proj<<<dim3(DIM / 128, MQ / 128), 256, GEMM_SMEM>>>(
        Oh, Ol, Wph, Wpl, out, bproj);
}

// round 12
// speedup vs baseline: 1.0658x; 1.0658x over previous
#include <cuda_runtime.h>
#include <cuda_bf16.h>
#include <cstdint>
#include <math.h>

#define DIM   768
#define HEADS 12
#define HD    64
#define BS    32
#define NMM   256
#define NV    196
#define NA    60
#define NSRC  256            // NV + NA
#define MQ    (BS * NMM)     // 8192

// ---------------------------------------------------------------------------
// Scratch (static __device__ globals; allocation is forbidden)
// ---------------------------------------------------------------------------
__device__ float g_attn_fallback[(size_t)BS * HEADS * NMM * NSRC];

__device__ __nv_bfloat16 g_Axmm_hi[(size_t)MQ * DIM];
__device__ __nv_bfloat16 g_Axmm_lo[(size_t)MQ * DIM];
__device__ __nv_bfloat16 g_Asrc_hi[(size_t)MQ * DIM];
__device__ __nv_bfloat16 g_Asrc_lo[(size_t)MQ * DIM];
__device__ __nv_bfloat16 g_Qh [(size_t)MQ * DIM];
__device__ __nv_bfloat16 g_Ql [(size_t)MQ * DIM];
__device__ __nv_bfloat16 g_KVh[(size_t)MQ * 2 * DIM];
__device__ __nv_bfloat16 g_KVl[(size_t)MQ * 2 * DIM];
__device__ __nv_bfloat16 g_Oh [(size_t)MQ * DIM];
__device__ __nv_bfloat16 g_Ol [(size_t)MQ * DIM];
__device__ __nv_bfloat16 g_Wqt_hi [(size_t)DIM * DIM];
__device__ __nv_bfloat16 g_Wqt_lo [(size_t)DIM * DIM];
__device__ __nv_bfloat16 g_Wkvt_hi[(size_t)2 * DIM * DIM];
__device__ __nv_bfloat16 g_Wkvt_lo[(size_t)2 * DIM * DIM];
__device__ __nv_bfloat16 g_Wpt_hi [(size_t)DIM * DIM];
__device__ __nv_bfloat16 g_Wpt_lo [(size_t)DIM * DIM];

// ---------------------------------------------------------------------------
// helpers
// ---------------------------------------------------------------------------
__device__ __forceinline__ uint32_t smem_u32(const void* p) {
    uint32_t a;
    asm("{ .reg .u64 t; cvta.to.shared.u64 t, %1; cvt.u32.u64 %0, t; }" : "=r"(a) : "l"(p));
    return a;
}
__device__ __forceinline__ uint32_t pack_bf2(__nv_bfloat16 a, __nv_bfloat16 b) {
    __nv_bfloat162 t = __halves2bfloat162(a, b);
    return *reinterpret_cast<uint32_t*>(&t);
}
__device__ __forceinline__ void split2(float a, float b, uint32_t& hi, uint32_t& lo) {
    __nv_bfloat16 ha = __float2bfloat16(a), hb = __float2bfloat16(b);
    hi = pack_bf2(ha, hb);
    lo = pack_bf2(__float2bfloat16(a - __bfloat162float(ha)),
                  __float2bfloat16(b - __bfloat162float(hb)));
}
__device__ __forceinline__ void cp_async16(uint32_t saddr, const void* gptr) {
    asm volatile("cp.async.cg.shared.global [%0], [%1], 16;" :: "r"(saddr), "l"(gptr));
}
__device__ __forceinline__ void cp_commit() { asm volatile("cp.async.commit_group;"); }
template<int N_>
__device__ __forceinline__ void cp_wait() { asm volatile("cp.async.wait_group %0;" :: "n"(N_)); }

__device__ __forceinline__ void mma16816(float* c, uint32_t a0, uint32_t a1,
                                         uint32_t a2, uint32_t a3,
                                         uint32_t b0, uint32_t b1) {
    asm volatile(
        "mma.sync.aligned.m16n8k16.row.col.f32.bf16.bf16.f32 "
        "{%0,%1,%2,%3}, {%4,%5,%6,%7}, {%8,%9}, {%0,%1,%2,%3};"
        : "+f"(c[0]), "+f"(c[1]), "+f"(c[2]), "+f"(c[3])
        : "r"(a0), "r"(a1), "r"(a2), "r"(a3), "r"(b0), "r"(b1));
}
__device__ __forceinline__ void ldmx4(uint32_t* r, uint32_t saddr) {
    asm volatile("ldmatrix.sync.aligned.m8n8.x4.shared.b16 {%0,%1,%2,%3}, [%4];"
                 : "=r"(r[0]), "=r"(r[1]), "=r"(r[2]), "=r"(r[3]) : "r"(saddr));
}
__device__ __forceinline__ void ldmx4t(uint32_t* r, uint32_t saddr) {
    asm volatile("ldmatrix.sync.aligned.m8n8.x4.trans.shared.b16 {%0,%1,%2,%3}, [%4];"
                 : "=r"(r[0]), "=r"(r[1]), "=r"(r[2]), "=r"(r[3]) : "r"(saddr));
}
__device__ __forceinline__ void st_cs_f2(float* p, float x, float y) {
    asm volatile("st.global.cs.v2.f32 [%0], {%1, %2};" :: "l"(p), "f"(x), "f"(y) : "memory");
}
__device__ __forceinline__ void split4(float4 x, uint2& hi, uint2& lo) {
    uint32_t h0, l0, h1, l1;
    split2(x.x, x.y, h0, l0);
    split2(x.z, x.w, h1, l1);
    hi = make_uint2(h0, h1);
    lo = make_uint2(l0, l1);
}

// ---------------------------------------------------------------------------
// Conversion kernels: fp32 -> (hi, lo) bf16 split (vectorized x4)
// ---------------------------------------------------------------------------
__global__ void split_plain_v4(const float4* __restrict__ X,
                               uint2* __restrict__ hi, uint2* __restrict__ lo,
                               size_t n4) {
    for (size_t i = (size_t)blockIdx.x * blockDim.x + threadIdx.x; i < n4;
         i += (size_t)gridDim.x * blockDim.x) {
        uint2 H, L;
        split4(X[i], H, L);
        hi[i] = H;
        lo[i] = L;
    }
}

__global__ void split_concat_v4(const float4* __restrict__ xv, const float4* __restrict__ xa,
                                uint2* __restrict__ hi, uint2* __restrict__ lo) {
    const int D4 = DIM / 4;
    size_t n4 = (size_t)MQ * D4;
    for (size_t i = (size_t)blockIdx.x * blockDim.x + threadIdx.x; i < n4;
         i += (size_t)gridDim.x * blockDim.x) {
        size_t row = i / D4, cg = i % D4;
        int b = (int)(row >> 8), t = (int)(row & 255);
        float4 x = (t < NV) ? xv[((size_t)b * NV + t) * D4 + cg]
                            : xa[((size_t)b * NA + (t - NV)) * D4 + cg];
        uint2 H, L;
        split4(x, H, L);
        hi[i] = H;
        lo[i] = L;
    }
}

// W [K][N] fp32 -> Wt [N][K] bf16 hi/lo
__global__ void transpose_split(const float* __restrict__ W,
                                __nv_bfloat16* __restrict__ Thi,
                                __nv_bfloat16* __restrict__ Tlo, int K, int N) {
    __shared__ float tile[32][33];
    int n0 = blockIdx.x * 32, k0 = blockIdx.y * 32;
    int tx = threadIdx.x, ty = threadIdx.y;     // (32, 8)
#pragma unroll
    for (int j = 0; j < 32; j += 8)
        tile[ty + j][tx] = W[(size_t)(k0 + ty + j) * N + (n0 + tx)];
    __syncthreads();
#pragma unroll
    for (int j = 0; j < 32; j += 8) {
        float v = tile[tx][ty + j];
        __nv_bfloat16 h = __float2bfloat16(v);
        size_t o = (size_t)(n0 + ty + j) * K + (k0 + tx);
        Thi[o] = h;
        Tlo[o] = __float2bfloat16(v - __bfloat162float(h));
    }
}

// ---------------------------------------------------------------------------
// HMMA split-bf16 GEMM: C[M,N] = A[M,K] @ Bt[N,K]^T ; K=768 compile-time.
// CTA 128x128, 8 warps 64x32, K-chunk 32, double buffer, ldmatrix frags.
// ---------------------------------------------------------------------------
#define CK       32
#define GK       768                        // compile-time K
#define SROW     40
#define TILE_BF  (128 * SROW)
#define ST_ELEMS (4 * TILE_BF)
#define GEMM_SMEM (2 * ST_ELEMS * 2)        // 81920 bytes

template<bool SPLIT, int NN>
__global__ void __launch_bounds__(256, 2) gemm_bf16s(
    const __nv_bfloat16* __restrict__ Ahi, const __nv_bfloat16* __restrict__ Alo,
    const __nv_bfloat16* __restrict__ Bhi, const __nv_bfloat16* __restrict__ Blo,
    float* __restrict__ C, __nv_bfloat16* __restrict__ Chi, __nv_bfloat16* __restrict__ Clo,
    const float* __restrict__ bias)
{
    extern __shared__ __align__(16) __nv_bfloat16 sm[];
    const int tid  = threadIdx.x;
    const int wid  = tid >> 5;
    const int lane = tid & 31;
    const int wm   = (wid >> 2) * 64;
    const int wn   = (wid & 3) * 32;
    const int m0   = blockIdx.y * 128;
    const int n0   = blockIdx.x * 128;
    constexpr int NC = GK / CK;             // 24

    const int lr = lane >> 2;
    const int lc = (lane & 3) * 2;

    const int arow = (lane & 7) + ((lane >> 3) & 1) * 8;
    const int akof = (lane >> 4) * 8;
    const int brow = (lane & 7) + ((lane >> 4) << 3);
    const int bkof = ((lane >> 3) & 1) * 8;

    float acc[4][4][4];
#pragma unroll
    for (int i = 0; i < 4; i++)
#pragma unroll
        for (int j = 0; j < 4; j++)
#pragma unroll
            for (int v = 0; v < 4; v++) acc[i][j][v] = 0.f;

    uint32_t smb = smem_u32(sm);
    const uint32_t offAh = (uint32_t)(0 * TILE_BF + (wm + arow) * SROW + akof) * 2;
    const uint32_t offAl = (uint32_t)(1 * TILE_BF + (wm + arow) * SROW + akof) * 2;
    const uint32_t offBh = (uint32_t)(2 * TILE_BF + (wn + brow) * SROW + bkof) * 2;
    const uint32_t offBl = (uint32_t)(3 * TILE_BF + (wn + brow) * SROW + bkof) * 2;

    auto load_chunk = [&](int c, int s) {
        uint32_t base = smb + (uint32_t)s * ST_ELEMS * 2;
        int k0 = c * CK;
#pragma unroll
        for (int it = 0; it < 2; it++) {
            int e   = tid + it * 256;
            int r   = e >> 2, seg = e & 3;
            uint32_t doff = (uint32_t)(r * SROW + seg * 8) * 2;
            size_t  goffA = (size_t)(m0 + r) * GK + k0 + seg * 8;
            size_t  goffB = (size_t)(n0 + r) * GK + k0 + seg * 8;
            cp_async16(base + 0 * TILE_BF * 2 + doff, Ahi + goffA);
            cp_async16(base + 1 * TILE_BF * 2 + doff, Alo + goffA);
            cp_async16(base + 2 * TILE_BF * 2 + doff, Bhi + goffB);
            cp_async16(base + 3 * TILE_BF * 2 + doff, Blo + goffB);
        }
        cp_commit();
    };

    load_chunk(0, 0);

#pragma unroll 2
    for (int c = 0; c < NC; c++) {
        int s = c & 1;
        if (c + 1 < NC) load_chunk(c + 1, (c + 1) & 1);
        if (c + 1 < NC) cp_wait<1>(); else cp_wait<0>();
        __syncthreads();

        uint32_t stg = smb + (uint32_t)s * ST_ELEMS * 2;

#pragma unroll
        for (int ks = 0; ks < 2; ks++) {
            uint32_t kbb = (uint32_t)(ks * 16) * 2;
            uint32_t bh[4][2], bl[4][2];
#pragma unroll
            for (int p = 0; p < 2; p++) {
                uint32_t t4[4];
                ldmx4(t4, stg + offBh + kbb + (uint32_t)(p * 16 * SROW) * 2);
                bh[2 * p][0] = t4[0]; bh[2 * p][1] = t4[1];
                bh[2 * p + 1][0] = t4[2]; bh[2 * p + 1][1] = t4[3];
                ldmx4(t4, stg + offBl + kbb + (uint32_t)(p * 16 * SROW) * 2);
                bl[2 * p][0] = t4[0]; bl[2 * p][1] = t4[1];
                bl[2 * p + 1][0] = t4[2]; bl[2 * p + 1][1] = t4[3];
            }
#pragma unroll
            for (int mt = 0; mt < 4; mt++) {
                uint32_t ah[4], al[4];
                ldmx4(ah, stg + offAh + kbb + (uint32_t)(mt * 16 * SROW) * 2);
                ldmx4(al, stg + offAl + kbb + (uint32_t)(mt * 16 * SROW) * 2);
#pragma unroll
                for (int nt = 0; nt < 4; nt++) {
                    mma16816(acc[mt][nt], ah[0], ah[1], ah[2], ah[3], bh[nt][0], bh[nt][1]);
                    mma16816(acc[mt][nt], ah[0], ah[1], ah[2], ah[3], bl[nt][0], bl[nt][1]);
                    mma16816(acc[mt][nt], al[0], al[1], al[2], al[3], bh[nt][0], bh[nt][1]);
                }
            }
        }
        __syncthreads();
    }

#pragma unroll
    for (int mt = 0; mt < 4; mt++) {
        int r0 = m0 + wm + mt * 16 + lr;
#pragma unroll
        for (int nt = 0; nt < 4; nt++) {
            int cc = n0 + wn + nt * 8 + lc;
            if (SPLIT) {
                uint32_t h0, l0, h1, l1;
                split2(acc[mt][nt][0], acc[mt][nt][1], h0, l0);
                split2(acc[mt][nt][2], acc[mt][nt][3], h1, l1);
                *(uint32_t*)(Chi + (size_t)r0 * NN + cc)       = h0;
                *(uint32_t*)(Clo + (size_t)r0 * NN + cc)       = l0;
                *(uint32_t*)(Chi + (size_t)(r0 + 8) * NN + cc) = h1;
                *(uint32_t*)(Clo + (size_t)(r0 + 8) * NN + cc) = l1;
            } else {
                float b0 = bias ? bias[cc]     : 0.f;
                float b1 = bias ? bias[cc + 1] : 0.f;
                float* p0 = C + (size_t)r0 * NN + cc;
                float* p1 = C + (size_t)(r0 + 8) * NN + cc;
                p0[0] = acc[mt][nt][0] + b0;
                p0[1] = acc[mt][nt][1] + b1;
                p1[0] = acc[mt][nt][2] + b0;
                p1[1] = acc[mt][nt][3] + b1;
            }
        }
    }
}

// ---------------------------------------------------------------------------
// HMMA flash-style attention. CTA = (q-tile 128, h, b), 256 thr (8 warps).
// Warp owns 16 q-rows x 256 keys. 3-term split everywhere. ldmatrix frags.
// ---------------------------------------------------------------------------
#define QSTR 72
#define AT_QH 0
#define AT_QL (128 * QSTR)
#define AT_KH (2 * 128 * QSTR)
#define AT_KL (AT_KH + 256 * QSTR)
#define AT_VH (AT_KH + 2 * 256 * QSTR)
#define AT_VL (AT_KH + 3 * 256 * QSTR)
#define AT_SMEM_ELE (AT_KH + 4 * 256 * QSTR)      // 92160 bf16
#define AT_SMEM_BYTES (AT_SMEM_ELE * 2)           // 184320

__global__ void __launch_bounds__(256) attn_mma(
    const __nv_bfloat16* __restrict__ Qhi, const __nv_bfloat16* __restrict__ Qlo,
    const __nv_bfloat16* __restrict__ KVhi, const __nv_bfloat16* __restrict__ KVlo,
    float* __restrict__ attn,
    __nv_bfloat16* __restrict__ Ohi, __nv_bfloat16* __restrict__ Olo)
{
    extern __shared__ __align__(16) __nv_bfloat16 asm_[];
    const int tid  = threadIdx.x;
    const int wid  = tid >> 5;
    const int lane = tid & 31;
    const int lr   = lane >> 2;
    const int lc   = lane & 3;
    const int b    = blockIdx.z;
    const int h    = blockIdx.y;
    const int q0   = blockIdx.x * 128;

    const int arow = (lane & 7) + ((lane >> 3) & 1) * 8;
    const int akof = (lane >> 4) * 8;
    const int brow = (lane & 7) + ((lane >> 4) << 3);
    const int bkof = ((lane >> 3) & 1) * 8;

    // ---- load tiles ----
    {
        const __nv_bfloat16* Qgh = Qhi + ((size_t)(b * NMM + q0)) * DIM + h * HD;
        const __nv_bfloat16* Qgl = Qlo + ((size_t)(b * NMM + q0)) * DIM + h * HD;
#pragma unroll
        for (int it = 0; it < 4; it++) {
            int e = tid + it * 256;
            int r = e >> 3, s = e & 7;
            *(uint4*)&asm_[AT_QH + r * QSTR + s * 8] = *(const uint4*)(Qgh + (size_t)r * DIM + s * 8);
            *(uint4*)&asm_[AT_QL + r * QSTR + s * 8] = *(const uint4*)(Qgl + (size_t)r * DIM + s * 8);
        }
        const __nv_bfloat16* Kgh = KVhi + ((size_t)b * NSRC) * (2 * DIM) + h * HD;
        const __nv_bfloat16* Kgl = KVlo + ((size_t)b * NSRC) * (2 * DIM) + h * HD;
#pragma unroll
        for (int it = 0; it < 8; it++) {
            int e = tid + it * 256;
            int r = e >> 3, s = e & 7;
            size_t go = (size_t)r * (2 * DIM) + s * 8;
            *(uint4*)&asm_[AT_KH + r * QSTR + s * 8] = *(const uint4*)(Kgh + go);
            *(uint4*)&asm_[AT_KL + r * QSTR + s * 8] = *(const uint4*)(Kgl + go);
            *(uint4*)&asm_[AT_VH + r * QSTR + s * 8] = *(const uint4*)(Kgh + go + DIM);
            *(uint4*)&asm_[AT_VL + r * QSTR + s * 8] = *(const uint4*)(Kgl + go + DIM);
        }
    }
    __syncthreads();

    uint32_t smb = smem_u32(asm_);

    // ---- Q fragments via ldmatrix.x4 ----
    uint32_t qh[4][4], ql[4][4];
    {
        uint32_t qoff = smb + (uint32_t)((wid * 16 + arow) * QSTR + akof) * 2;
#pragma unroll
        for (int kt = 0; kt < 4; kt++) {
            ldmx4(qh[kt], qoff + (uint32_t)(AT_QH * 2) + kt * 32);
            ldmx4(ql[kt], qoff + (uint32_t)(AT_QL * 2) + kt * 32);
        }
    }

    // ---- S = Q K^T (3-term split), K frags via ldmatrix.x4 ----
    float acc[32][4];
#pragma unroll
    for (int t = 0; t < 32; t++)
#pragma unroll
        for (int v = 0; v < 4; v++) acc[t][v] = 0.f;

    {
        uint32_t kbase = smb + (uint32_t)(brow * QSTR + bkof) * 2;
#pragma unroll
        for (int p = 0; p < 16; p++) {         // 16 key-pairs (16 keys each)
            uint32_t prow = kbase + (uint32_t)(p * 16 * QSTR) * 2;
#pragma unroll
            for (int kt = 0; kt < 4; kt++) {
                uint32_t kh4[4], kl4[4];
                ldmx4(kh4, prow + (uint32_t)(AT_KH * 2) + kt * 32);
                ldmx4(kl4, prow + (uint32_t)(AT_KL * 2) + kt * 32);
                mma16816(acc[2 * p],     qh[kt][0], qh[kt][1], qh[kt][2], qh[kt][3], kh4[0], kh4[1]);
                mma16816(acc[2 * p],     qh[kt][0], qh[kt][1], qh[kt][2], qh[kt][3], kl4[0], kl4[1]);
                mma16816(acc[2 * p],     ql[kt][0], ql[kt][1], ql[kt][2], ql[kt][3], kh4[0], kh4[1]);
                mma16816(acc[2 * p + 1], qh[kt][0], qh[kt][1], qh[kt][2], qh[kt][3], kh4[2], kh4[3]);
                mma16816(acc[2 * p + 1], qh[kt][0], qh[kt][1], qh[kt][2], qh[kt][3], kl4[2], kl4[3]);
                mma16816(acc[2 * p + 1], ql[kt][0], ql[kt][1], ql[kt][2], ql[kt][3], kh4[2], kh4[3]);
            }
        }
    }

    // ---- softmax (rows lr and lr+8 of this warp's 16) ----
    const float scale = 0.125f;
    float mx0 = -1e30f, mx1 = -1e30f;
#pragma unroll
    for (int t = 0; t < 32; t++) {
        mx0 = fmaxf(mx0, fmaxf(acc[t][0], acc[t][1]));
        mx1 = fmaxf(mx1, fmaxf(acc[t][2], acc[t][3]));
    }
    mx0 = fmaxf(mx0, __shfl_xor_sync(0xffffffffu, mx0, 1));
    mx0 = fmaxf(mx0, __shfl_xor_sync(0xffffffffu, mx0, 2));
    mx1 = fmaxf(mx1, __shfl_xor_sync(0xffffffffu, mx1, 1));
    mx1 = fmaxf(mx1, __shfl_xor_sync(0xffffffffu, mx1, 2));
    float s0 = 0.f, s1 = 0.f;
#pragma unroll
    for (int t = 0; t < 32; t++) {
        acc[t][0] = __expf((acc[t][0] - mx0) * scale); s0 += acc[t][0];
        acc[t][1] = __expf((acc[t][1] - mx0) * scale); s0 += acc[t][1];
        acc[t][2] = __expf((acc[t][2] - mx1) * scale); s1 += acc[t][2];
        acc[t][3] = __expf((acc[t][3] - mx1) * scale); s1 += acc[t][3];
    }
    s0 += __shfl_xor_sync(0xffffffffu, s0, 1);
    s0 += __shfl_xor_sync(0xffffffffu, s0, 2);
    s1 += __shfl_xor_sync(0xffffffffu, s1, 1);
    s1 += __shfl_xor_sync(0xffffffffu, s1, 2);
    float i0 = 1.f / s0, i1 = 1.f / s1;
#pragma unroll
    for (int t = 0; t < 32; t++) {
        acc[t][0] *= i0; acc[t][1] *= i0; acc[t][2] *= i1; acc[t][3] *= i1;
    }

    // ---- write attn probs (fp32, global, streaming) ----
    {
        float* ar0 = attn + ((size_t)((b * HEADS + h) * NMM) + q0 + wid * 16 + lr) * NSRC + 2 * lc;
        float* ar1 = ar0 + (size_t)8 * NSRC;
#pragma unroll
        for (int t = 0; t < 32; t++) {
            st_cs_f2(ar0 + t * 8, acc[t][0], acc[t][1]);
            st_cs_f2(ar1 + t * 8, acc[t][2], acc[t][3]);
        }
    }

    // ---- convert P to bf16 hi/lo A-fragments ----
    uint32_t ph[16][4], pl[16][4];
#pragma unroll
    for (int t = 0; t < 16; t++) {
        split2(acc[2 * t][0],     acc[2 * t][1],     ph[t][0], pl[t][0]);
        split2(acc[2 * t][2],     acc[2 * t][3],     ph[t][1], pl[t][1]);
        split2(acc[2 * t + 1][0], acc[2 * t + 1][1], ph[t][2], pl[t][2]);
        split2(acc[2 * t + 1][2], acc[2 * t + 1][3], ph[t][3], pl[t][3]);
    }

    // ---- O = P V (3-term split), V B-frags via ldmatrix.x4.trans ----
    float oacc[8][4];
#pragma unroll
    for (int nd = 0; nd < 8; nd++)
#pragma unroll
        for (int v = 0; v < 4; v++) oacc[nd][v] = 0.f;

    {
        uint32_t vbase = smb + (uint32_t)((lane & 15) * QSTR + (lane >> 4) * 8) * 2;
#pragma unroll
        for (int kt = 0; kt < 16; kt++) {
            uint32_t vrow = vbase + (uint32_t)(kt * 16 * QSTR) * 2;
#pragma unroll
            for (int ndp = 0; ndp < 4; ndp++) {
                uint32_t vh4[4], vl4[4];
                ldmx4t(vh4, vrow + (uint32_t)(AT_VH * 2) + ndp * 32);
                ldmx4t(vl4, vrow + (uint32_t)(AT_VL * 2) + ndp * 32);
                mma16816(oacc[2 * ndp],     ph[kt][0], ph[kt][1], ph[kt][2], ph[kt][3], vh4[0], vh4[1]);
                mma16816(oacc[2 * ndp],     ph[kt][0], ph[kt][1], ph[kt][2], ph[kt][3], vl4[0], vl4[1]);
                mma16816(oacc[2 * ndp],     pl[kt][0], pl[kt][1], pl[kt][2], pl[kt][3], vh4[0], vh4[1]);
                mma16816(oacc[2 * ndp + 1], ph[kt][0], ph[kt][1], ph[kt][2], ph[kt][3], vh4[2], vh4[3]);
                mma16816(oacc[2 * ndp + 1], ph[kt][0], ph[kt][1], ph[kt][2], ph[kt][3], vl4[2], vl4[3]);
                mma16816(oacc[2 * ndp + 1], pl[kt][0], pl[kt][1], pl[kt][2], pl[kt][3], vh4[2], vh4[3]);
            }
        }
    }

    // ---- write O as bf16 hi/lo ----
    {
        size_t row0 = (size_t)(b * NMM + q0 + wid * 16 + lr);
        __nv_bfloat16* oh0 = Ohi + row0 * DIM + h * HD + 2 * lc;
        __nv_bfloat16* ol0 = Olo + row0 * DIM + h * HD + 2 * lc;
        __nv_bfloat16* oh1 = oh0 + (size_t)8 * DIM;
        __nv_bfloat16* ol1 = ol0 + (size_t)8 * DIM;
#pragma unroll
        for (int nd = 0; nd < 8; nd++) {
            uint32_t hh, ll;
            split2(oacc[nd][0], oacc[nd][1], hh, ll);
            *(uint32_t*)(oh0 + nd * 8) = hh;
            *(uint32_t*)(ol0 + nd * 8) = ll;
            split2(oacc[nd][2], oacc[nd][3], hh, ll);
            *(uint32_t*)(oh1 + nd * 8) = hh;
            *(uint32_t*)(ol1 + nd * 8) = ll;
        }
    }
}

// ---------------------------------------------------------------------------
extern "C" void kernel_launch(void* const* d_in, const int* in_sizes, int n_in,
                              void* d_out, int out_size)
{
    const float* xmm   = (const float*)d_in[0];
    const float* xv    = (const float*)d_in[1];
    const float* xa    = (const float*)d_in[2];
    const float* Wq    = (const float*)d_in[3];
    const float* Wkv   = (const float*)d_in[4];
    const float* Wproj = (const float*)d_in[5];
    const float* bproj = (const float*)d_in[6];

    float* out = (float*)d_out;

    float* attn_fb;
    cudaGetSymbolAddress((void**)&attn_fb, g_attn_fallback);

    __nv_bfloat16 *Axh, *Axl, *Ash, *Asl;
    __nv_bfloat16 *Qh, *Ql, *KVh, *KVl, *Oh, *Ol;
    __nv_bfloat16 *Wqh, *Wql, *Wkh, *Wkl, *Wph, *Wpl;
    cudaGetSymbolAddress((void**)&Axh, g_Axmm_hi);
    cudaGetSymbolAddress((void**)&Axl, g_Axmm_lo);
    cudaGetSymbolAddress((void**)&Ash, g_Asrc_hi);
    cudaGetSymbolAddress((void**)&Asl, g_Asrc_lo);
    cudaGetSymbolAddress((void**)&Qh,  g_Qh);
    cudaGetSymbolAddress((void**)&Ql,  g_Ql);
    cudaGetSymbolAddress((void**)&KVh, g_KVh);
    cudaGetSymbolAddress((void**)&KVl, g_KVl);
    cudaGetSymbolAddress((void**)&Oh,  g_Oh);
    cudaGetSymbolAddress((void**)&Ol,  g_Ol);
    cudaGetSymbolAddress((void**)&Wqh, g_Wqt_hi);
    cudaGetSymbolAddress((void**)&Wql, g_Wqt_lo);
    cudaGetSymbolAddress((void**)&Wkh, g_Wkvt_hi);
    cudaGetSymbolAddress((void**)&Wkl, g_Wkvt_lo);
    cudaGetSymbolAddress((void**)&Wph, g_Wpt_hi);
    cudaGetSymbolAddress((void**)&Wpl, g_Wpt_lo);

    const size_t out_elems  = (size_t)MQ * DIM;
    const size_t attn_elems = (size_t)BS * HEADS * NMM * NSRC;
    float* attn_out = ((size_t)out_size >= out_elems + attn_elems)
                        ? out + out_elems : attn_fb;

    cudaFuncSetAttribute((const void*)gemm_bf16s<true, DIM>,
                         cudaFuncAttributeMaxDynamicSharedMemorySize, GEMM_SMEM);
    cudaFuncSetAttribute((const void*)gemm_bf16s<true, 2 * DIM>,
                         cudaFuncAttributeMaxDynamicSharedMemorySize, GEMM_SMEM);
    cudaFuncSetAttribute((const void*)gemm_bf16s<false, DIM>,
                         cudaFuncAttributeMaxDynamicSharedMemorySize, GEMM_SMEM);
    cudaFuncSetAttribute(attn_mma, cudaFuncAttributeMaxDynamicSharedMemorySize, AT_SMEM_BYTES);

    // --- conversions ---
    {
        dim3 bb(32, 8);
        transpose_split<<<dim3(DIM / 32, DIM / 32), bb>>>(Wq, Wqh, Wql, DIM, DIM);
        transpose_split<<<dim3(2 * DIM / 32, DIM / 32), bb>>>(Wkv, Wkh, Wkl, DIM, 2 * DIM);
        transpose_split<<<dim3(DIM / 32, DIM / 32), bb>>>(Wproj, Wph, Wpl, DIM, DIM);
    }
    split_plain_v4<<<1024, 256>>>((const float4*)xmm, (uint2*)Axh, (uint2*)Axl,
                                  (size_t)MQ * DIM / 4);
    split_concat_v4<<<1024, 256>>>((const float4*)xv, (const float4*)xa,
                                   (uint2*)Ash, (uint2*)Asl);

    // --- Q = xmm @ Wq  -> bf16 hi/lo ---
    gemm_bf16s<true, DIM><<<dim3(DIM / 128, MQ / 128), 256, GEMM_SMEM>>>(
        Axh, Axl, Wqh, Wql, nullptr, Qh, Ql, nullptr);
    // --- KV = concat(xv,xa) @ Wkv -> bf16 hi/lo ---
    gemm_bf16s<true, 2 * DIM><<<dim3(2 * DIM / 128, MQ / 128), 256, GEMM_SMEM>>>(
        Ash, Asl, Wkh, Wkl, nullptr, KVh, KVl, nullptr);
    // --- attention ---
    attn_mma<<<dim3(NMM / 128, HEADS, BS), 256, AT_SMEM_BYTES>>>(
        Qh, Ql, KVh, KVl, attn_out, Oh, Ol);
    // --- out = O @ Wproj + bproj (fp32) ---
    gemm_bf16s<false, DIM><<<dim3(DIM / 128, MQ / 128), 256, GEMM_SMEM>>>(
        Oh, Ol, Wph, Wpl, out, nullptr, nullptr, bproj);
}

// round 13
// speedup vs baseline: 1.0930x; 1.0256x over previous
#include <cuda_runtime.h>
#include <cuda_bf16.h>
#include <cstdint>
#include <math.h>

#define DIM   768
#define HEADS 12
#define HD    64
#define BS    32
#define NMM   256
#define NV    196
#define NA    60
#define NSRC  256            // NV + NA
#define MQ    (BS * NMM)     // 8192

// ---------------------------------------------------------------------------
// Scratch (static __device__ globals; allocation is forbidden)
// ---------------------------------------------------------------------------
__device__ float g_attn_fallback[(size_t)BS * HEADS * NMM * NSRC];

__device__ __nv_bfloat16 g_Axmm_hi[(size_t)MQ * DIM];
__device__ __nv_bfloat16 g_Axmm_lo[(size_t)MQ * DIM];
__device__ __nv_bfloat16 g_Asrc_hi[(size_t)MQ * DIM];
__device__ __nv_bfloat16 g_Asrc_lo[(size_t)MQ * DIM];
__device__ __nv_bfloat16 g_Qh [(size_t)MQ * DIM];
__device__ __nv_bfloat16 g_Ql [(size_t)MQ * DIM];
__device__ __nv_bfloat16 g_KVh[(size_t)MQ * 2 * DIM];
__device__ __nv_bfloat16 g_KVl[(size_t)MQ * 2 * DIM];
__device__ __nv_bfloat16 g_Oh [(size_t)MQ * DIM];
__device__ __nv_bfloat16 g_Ol [(size_t)MQ * DIM];
__device__ __nv_bfloat16 g_Wqt_hi [(size_t)DIM * DIM];
__device__ __nv_bfloat16 g_Wqt_lo [(size_t)DIM * DIM];
__device__ __nv_bfloat16 g_Wkvt_hi[(size_t)2 * DIM * DIM];
__device__ __nv_bfloat16 g_Wkvt_lo[(size_t)2 * DIM * DIM];
__device__ __nv_bfloat16 g_Wpt_hi [(size_t)DIM * DIM];
__device__ __nv_bfloat16 g_Wpt_lo [(size_t)DIM * DIM];

// ---------------------------------------------------------------------------
// helpers
// ---------------------------------------------------------------------------
__device__ __forceinline__ uint32_t smem_u32(const void* p) {
    uint32_t a;
    asm("{ .reg .u64 t; cvta.to.shared.u64 t, %1; cvt.u32.u64 %0, t; }" : "=r"(a) : "l"(p));
    return a;
}
__device__ __forceinline__ uint32_t pack_bf2(__nv_bfloat16 a, __nv_bfloat16 b) {
    __nv_bfloat162 t = __halves2bfloat162(a, b);
    return *reinterpret_cast<uint32_t*>(&t);
}
__device__ __forceinline__ void split2(float a, float b, uint32_t& hi, uint32_t& lo) {
    __nv_bfloat16 ha = __float2bfloat16(a), hb = __float2bfloat16(b);
    hi = pack_bf2(ha, hb);
    lo = pack_bf2(__float2bfloat16(a - __bfloat162float(ha)),
                  __float2bfloat16(b - __bfloat162float(hb)));
}
__device__ __forceinline__ void cp_async16(uint32_t saddr, const void* gptr) {
    asm volatile("cp.async.cg.shared.global [%0], [%1], 16;" :: "r"(saddr), "l"(gptr));
}
__device__ __forceinline__ void cp_commit() { asm volatile("cp.async.commit_group;"); }
template<int N_>
__device__ __forceinline__ void cp_wait() { asm volatile("cp.async.wait_group %0;" :: "n"(N_)); }

__device__ __forceinline__ void mma16816(float* c, uint32_t a0, uint32_t a1,
                                         uint32_t a2, uint32_t a3,
                                         uint32_t b0, uint32_t b1) {
    asm volatile(
        "mma.sync.aligned.m16n8k16.row.col.f32.bf16.bf16.f32 "
        "{%0,%1,%2,%3}, {%4,%5,%6,%7}, {%8,%9}, {%0,%1,%2,%3};"
        : "+f"(c[0]), "+f"(c[1]), "+f"(c[2]), "+f"(c[3])
        : "r"(a0), "r"(a1), "r"(a2), "r"(a3), "r"(b0), "r"(b1));
}
__device__ __forceinline__ void ldmx4(uint32_t* r, uint32_t saddr) {
    asm volatile("ldmatrix.sync.aligned.m8n8.x4.shared.b16 {%0,%1,%2,%3}, [%4];"
                 : "=r"(r[0]), "=r"(r[1]), "=r"(r[2]), "=r"(r[3]) : "r"(saddr));
}
__device__ __forceinline__ void ldmx4t(uint32_t* r, uint32_t saddr) {
    asm volatile("ldmatrix.sync.aligned.m8n8.x4.trans.shared.b16 {%0,%1,%2,%3}, [%4];"
                 : "=r"(r[0]), "=r"(r[1]), "=r"(r[2]), "=r"(r[3]) : "r"(saddr));
}
__device__ __forceinline__ void st_cs_f2(float* p, float x, float y) {
    asm volatile("st.global.cs.v2.f32 [%0], {%1, %2};" :: "l"(p), "f"(x), "f"(y) : "memory");
}
__device__ __forceinline__ void split4(float4 x, uint2& hi, uint2& lo) {
    uint32_t h0, l0, h1, l1;
    split2(x.x, x.y, h0, l0);
    split2(x.z, x.w, h1, l1);
    hi = make_uint2(h0, h1);
    lo = make_uint2(l0, l1);
}

// ---------------------------------------------------------------------------
// Merged conversion kernels
// ---------------------------------------------------------------------------
// z=0: xmm -> Axmm ; z=1: concat(xv,xa) -> Asrc
__global__ void split_all_v4(const float4* __restrict__ xmm,
                             const float4* __restrict__ xv, const float4* __restrict__ xa,
                             uint2* __restrict__ xh, uint2* __restrict__ xl,
                             uint2* __restrict__ sh, uint2* __restrict__ sl) {
    const int D4 = DIM / 4;
    size_t n4 = (size_t)MQ * D4;
    if (blockIdx.y == 0) {
        for (size_t i = (size_t)blockIdx.x * blockDim.x + threadIdx.x; i < n4;
             i += (size_t)gridDim.x * blockDim.x) {
            uint2 H, L;
            split4(xmm[i], H, L);
            xh[i] = H;
            xl[i] = L;
        }
    } else {
        for (size_t i = (size_t)blockIdx.x * blockDim.x + threadIdx.x; i < n4;
             i += (size_t)gridDim.x * blockDim.x) {
            size_t row = i / D4, cg = i % D4;
            int b = (int)(row >> 8), t = (int)(row & 255);
            float4 x = (t < NV) ? xv[((size_t)b * NV + t) * D4 + cg]
                                : xa[((size_t)b * NA + (t - NV)) * D4 + cg];
            uint2 H, L;
            split4(x, H, L);
            sh[i] = H;
            sl[i] = L;
        }
    }
}

// z selects weight matrix: 0 = Wq, 1 = Wkv, 2 = Wproj
__global__ void transpose_split_all(
    const float* __restrict__ Wq,  __nv_bfloat16* __restrict__ Qh_, __nv_bfloat16* __restrict__ Ql_,
    const float* __restrict__ Wkv, __nv_bfloat16* __restrict__ Kh_, __nv_bfloat16* __restrict__ Kl_,
    const float* __restrict__ Wp,  __nv_bfloat16* __restrict__ Ph_, __nv_bfloat16* __restrict__ Pl_)
{
    __shared__ float tile[32][33];
    int z = blockIdx.z;
    int N = (z == 1) ? 2 * DIM : DIM;
    if (blockIdx.x * 32 >= N) return;
    const float* W = (z == 0) ? Wq : (z == 1) ? Wkv : Wp;
    __nv_bfloat16* Thi = (z == 0) ? Qh_ : (z == 1) ? Kh_ : Ph_;
    __nv_bfloat16* Tlo = (z == 0) ? Ql_ : (z == 1) ? Kl_ : Pl_;

    int n0 = blockIdx.x * 32, k0 = blockIdx.y * 32;
    int tx = threadIdx.x, ty = threadIdx.y;     // (32, 8)
#pragma unroll
    for (int j = 0; j < 32; j += 8)
        tile[ty + j][tx] = W[(size_t)(k0 + ty + j) * N + (n0 + tx)];
    __syncthreads();
#pragma unroll
    for (int j = 0; j < 32; j += 8) {
        float v = tile[tx][ty + j];
        __nv_bfloat16 h = __float2bfloat16(v);
        size_t o = (size_t)(n0 + ty + j) * DIM + (k0 + tx);   // K == DIM always
        Thi[o] = h;
        Tlo[o] = __float2bfloat16(v - __bfloat162float(h));
    }
}

// ---------------------------------------------------------------------------
// HMMA split-bf16 GEMM: C[M,N] = A[M,K] @ Bt[N,K]^T ; K=768 compile-time.
// CTA 128x128, 8 warps 64x32, K-chunk 32, double buffer, ldmatrix frags.
// ---------------------------------------------------------------------------
#define CK       32
#define GK       768                        // compile-time K
#define SROW     40
#define TILE_BF  (128 * SROW)
#define ST_ELEMS (4 * TILE_BF)
#define GEMM_SMEM (2 * ST_ELEMS * 2)        // 81920 bytes

template<bool SPLIT, int NN>
__global__ void __launch_bounds__(256, 2) gemm_bf16s(
    const __nv_bfloat16* __restrict__ Ahi, const __nv_bfloat16* __restrict__ Alo,
    const __nv_bfloat16* __restrict__ Bhi, const __nv_bfloat16* __restrict__ Blo,
    float* __restrict__ C, __nv_bfloat16* __restrict__ Chi, __nv_bfloat16* __restrict__ Clo,
    const float* __restrict__ bias)
{
    extern __shared__ __align__(16) __nv_bfloat16 sm[];
    const int tid  = threadIdx.x;
    const int wid  = tid >> 5;
    const int lane = tid & 31;
    const int wm   = (wid >> 2) * 64;
    const int wn   = (wid & 3) * 32;
    const int m0   = blockIdx.y * 128;
    const int n0   = blockIdx.x * 128;
    constexpr int NC = GK / CK;             // 24

    const int lr = lane >> 2;
    const int lc = (lane & 3) * 2;

    const int arow = (lane & 7) + ((lane >> 3) & 1) * 8;
    const int akof = (lane >> 4) * 8;
    const int brow = (lane & 7) + ((lane >> 4) << 3);
    const int bkof = ((lane >> 3) & 1) * 8;

    float acc[4][4][4];
#pragma unroll
    for (int i = 0; i < 4; i++)
#pragma unroll
        for (int j = 0; j < 4; j++)
#pragma unroll
            for (int v = 0; v < 4; v++) acc[i][j][v] = 0.f;

    uint32_t smb = smem_u32(sm);
    const uint32_t offAh = (uint32_t)(0 * TILE_BF + (wm + arow) * SROW + akof) * 2;
    const uint32_t offAl = (uint32_t)(1 * TILE_BF + (wm + arow) * SROW + akof) * 2;
    const uint32_t offBh = (uint32_t)(2 * TILE_BF + (wn + brow) * SROW + bkof) * 2;
    const uint32_t offBl = (uint32_t)(3 * TILE_BF + (wn + brow) * SROW + bkof) * 2;

    auto load_chunk = [&](int c, int s) {
        uint32_t base = smb + (uint32_t)s * ST_ELEMS * 2;
        int k0 = c * CK;
#pragma unroll
        for (int it = 0; it < 2; it++) {
            int e   = tid + it * 256;
            int r   = e >> 2, seg = e & 3;
            uint32_t doff = (uint32_t)(r * SROW + seg * 8) * 2;
            size_t  goffA = (size_t)(m0 + r) * GK + k0 + seg * 8;
            size_t  goffB = (size_t)(n0 + r) * GK + k0 + seg * 8;
            cp_async16(base + 0 * TILE_BF * 2 + doff, Ahi + goffA);
            cp_async16(base + 1 * TILE_BF * 2 + doff, Alo + goffA);
            cp_async16(base + 2 * TILE_BF * 2 + doff, Bhi + goffB);
            cp_async16(base + 3 * TILE_BF * 2 + doff, Blo + goffB);
        }
        cp_commit();
    };

    load_chunk(0, 0);

#pragma unroll 2
    for (int c = 0; c < NC; c++) {
        int s = c & 1;
        if (c + 1 < NC) load_chunk(c + 1, (c + 1) & 1);
        if (c + 1 < NC) cp_wait<1>(); else cp_wait<0>();
        __syncthreads();

        uint32_t stg = smb + (uint32_t)s * ST_ELEMS * 2;

#pragma unroll
        for (int ks = 0; ks < 2; ks++) {
            uint32_t kbb = (uint32_t)(ks * 16) * 2;
            uint32_t bh[4][2], bl[4][2];
#pragma unroll
            for (int p = 0; p < 2; p++) {
                uint32_t t4[4];
                ldmx4(t4, stg + offBh + kbb + (uint32_t)(p * 16 * SROW) * 2);
                bh[2 * p][0] = t4[0]; bh[2 * p][1] = t4[1];
                bh[2 * p + 1][0] = t4[2]; bh[2 * p + 1][1] = t4[3];
                ldmx4(t4, stg + offBl + kbb + (uint32_t)(p * 16 * SROW) * 2);
                bl[2 * p][0] = t4[0]; bl[2 * p][1] = t4[1];
                bl[2 * p + 1][0] = t4[2]; bl[2 * p + 1][1] = t4[3];
            }
#pragma unroll
            for (int mt = 0; mt < 4; mt++) {
                uint32_t ah[4], al[4];
                ldmx4(ah, stg + offAh + kbb + (uint32_t)(mt * 16 * SROW) * 2);
                ldmx4(al, stg + offAl + kbb + (uint32_t)(mt * 16 * SROW) * 2);
#pragma unroll
                for (int nt = 0; nt < 4; nt++) {
                    mma16816(acc[mt][nt], ah[0], ah[1], ah[2], ah[3], bh[nt][0], bh[nt][1]);
                    mma16816(acc[mt][nt], ah[0], ah[1], ah[2], ah[3], bl[nt][0], bl[nt][1]);
                    mma16816(acc[mt][nt], al[0], al[1], al[2], al[3], bh[nt][0], bh[nt][1]);
                }
            }
        }
        __syncthreads();
    }

#pragma unroll
    for (int mt = 0; mt < 4; mt++) {
        int r0 = m0 + wm + mt * 16 + lr;
#pragma unroll
        for (int nt = 0; nt < 4; nt++) {
            int cc = n0 + wn + nt * 8 + lc;
            if (SPLIT) {
                uint32_t h0, l0, h1, l1;
                split2(acc[mt][nt][0], acc[mt][nt][1], h0, l0);
                split2(acc[mt][nt][2], acc[mt][nt][3], h1, l1);
                *(uint32_t*)(Chi + (size_t)r0 * NN + cc)       = h0;
                *(uint32_t*)(Clo + (size_t)r0 * NN + cc)       = l0;
                *(uint32_t*)(Chi + (size_t)(r0 + 8) * NN + cc) = h1;
                *(uint32_t*)(Clo + (size_t)(r0 + 8) * NN + cc) = l1;
            } else {
                float b0 = bias ? bias[cc]     : 0.f;
                float b1 = bias ? bias[cc + 1] : 0.f;
                float* p0 = C + (size_t)r0 * NN + cc;
                float* p1 = C + (size_t)(r0 + 8) * NN + cc;
                p0[0] = acc[mt][nt][0] + b0;
                p0[1] = acc[mt][nt][1] + b1;
                p1[0] = acc[mt][nt][2] + b0;
                p1[1] = acc[mt][nt][3] + b1;
            }
        }
    }
}

// ---------------------------------------------------------------------------
// HMMA flash-style attention, chunked cp.async pipeline.
// CTA = (q-tile 128, h, b), 256 thr (8 warps). Warp owns 16 q-rows x 256 keys.
// smem: Q (hi/lo) + two 128-key K/V buffers (hi/lo). 110,592 bytes.
// Pipeline: K0|K1 async -> S0 -> V0 overlaps S1 -> V1 overlaps softmax/store
//           -> PV0 -> PV1.
// ---------------------------------------------------------------------------
#define QSTR 72
#define AT_QH   0
#define AT_QL   (128 * QSTR)                 // 9216
#define AT_BUF0 (2 * 128 * QSTR)             // 18432
#define AT_BUF1 (AT_BUF0 + 2 * 128 * QSTR)   // 36864
#define AT_LOFF (128 * QSTR)                 // lo offset within a buffer
#define AT_SMEM_ELE (AT_BUF1 + 2 * 128 * QSTR)   // 55296 bf16
#define AT_SMEM_BYTES (AT_SMEM_ELE * 2)          // 110592

__global__ void __launch_bounds__(256) attn_mma(
    const __nv_bfloat16* __restrict__ Qhi, const __nv_bfloat16* __restrict__ Qlo,
    const __nv_bfloat16* __restrict__ KVhi, const __nv_bfloat16* __restrict__ KVlo,
    float* __restrict__ attn,
    __nv_bfloat16* __restrict__ Ohi, __nv_bfloat16* __restrict__ Olo)
{
    extern __shared__ __align__(16) __nv_bfloat16 asm_[];
    const int tid  = threadIdx.x;
    const int wid  = tid >> 5;
    const int lane = tid & 31;
    const int lr   = lane >> 2;
    const int lc   = lane & 3;
    const int b    = blockIdx.z;
    const int h    = blockIdx.y;
    const int q0   = blockIdx.x * 128;

    const int arow = (lane & 7) + ((lane >> 3) & 1) * 8;
    const int akof = (lane >> 4) * 8;
    const int brow = (lane & 7) + ((lane >> 4) << 3);
    const int bkof = ((lane >> 3) & 1) * 8;

    uint32_t smb = smem_u32(asm_);

    // cp.async loader for a 128-key chunk of K or V (hi+lo) into a buffer
    auto load_kv = [&](int key0, int is_v, uint32_t bufoff) {
        const __nv_bfloat16* sh = KVhi + ((size_t)b * NSRC + key0) * (2 * DIM) + h * HD + is_v * DIM;
        const __nv_bfloat16* sl = KVlo + ((size_t)b * NSRC + key0) * (2 * DIM) + h * HD + is_v * DIM;
#pragma unroll
        for (int it = 0; it < 4; it++) {
            int e = tid + it * 256;
            int r = e >> 3, s = e & 7;
            size_t go = (size_t)r * (2 * DIM) + s * 8;
            uint32_t doff = (uint32_t)(r * QSTR + s * 8) * 2;
            cp_async16(smb + (bufoff * 2) + doff, sh + go);
            cp_async16(smb + ((bufoff + AT_LOFF) * 2) + doff, sl + go);
        }
        cp_commit();
    };

    // ---- prologue: async K0, K1; regular Q ----
    load_kv(0,   0, AT_BUF0);     // group 1
    load_kv(128, 0, AT_BUF1);     // group 2
    {
        const __nv_bfloat16* Qgh = Qhi + ((size_t)(b * NMM + q0)) * DIM + h * HD;
        const __nv_bfloat16* Qgl = Qlo + ((size_t)(b * NMM + q0)) * DIM + h * HD;
#pragma unroll
        for (int it = 0; it < 4; it++) {
            int e = tid + it * 256;
            int r = e >> 3, s = e & 7;
            *(uint4*)&asm_[AT_QH + r * QSTR + s * 8] = *(const uint4*)(Qgh + (size_t)r * DIM + s * 8);
            *(uint4*)&asm_[AT_QL + r * QSTR + s * 8] = *(const uint4*)(Qgl + (size_t)r * DIM + s * 8);
        }
    }
    cp_wait<1>();          // K0 arrived (K1 may be in flight)
    __syncthreads();

    // ---- Q fragments via ldmatrix.x4 ----
    uint32_t qh[4][4], ql[4][4];
    {
        uint32_t qoff = smb + (uint32_t)((wid * 16 + arow) * QSTR + akof) * 2;
#pragma unroll
        for (int kt = 0; kt < 4; kt++) {
            ldmx4(qh[kt], qoff + (uint32_t)(AT_QH * 2) + kt * 32);
            ldmx4(ql[kt], qoff + (uint32_t)(AT_QL * 2) + kt * 32);
        }
    }

    float acc[32][4];
#pragma unroll
    for (int t = 0; t < 32; t++)
#pragma unroll
        for (int v = 0; v < 4; v++) acc[t][v] = 0.f;

    // S over one 128-key chunk (8 key-pairs) in buffer bufoff -> acc[accb..accb+15]
    auto s_chunk = [&](uint32_t bufoff, int accb) {
        uint32_t kb = smb + (uint32_t)(bufoff + brow * QSTR + bkof) * 2;
#pragma unroll
        for (int p = 0; p < 8; p++) {
            uint32_t prow = kb + (uint32_t)(p * 16 * QSTR) * 2;
            float* a0 = acc[accb + 2 * p];
            float* a1 = acc[accb + 2 * p + 1];
#pragma unroll
            for (int kt = 0; kt < 4; kt++) {
                uint32_t kh4[4], kl4[4];
                ldmx4(kh4, prow + kt * 32);
                ldmx4(kl4, prow + (uint32_t)(AT_LOFF * 2) + kt * 32);
                mma16816(a0, qh[kt][0], qh[kt][1], qh[kt][2], qh[kt][3], kh4[0], kh4[1]);
                mma16816(a0, qh[kt][0], qh[kt][1], qh[kt][2], qh[kt][3], kl4[0], kl4[1]);
                mma16816(a0, ql[kt][0], ql[kt][1], ql[kt][2], ql[kt][3], kh4[0], kh4[1]);
                mma16816(a1, qh[kt][0], qh[kt][1], qh[kt][2], qh[kt][3], kh4[2], kh4[3]);
                mma16816(a1, qh[kt][0], qh[kt][1], qh[kt][2], qh[kt][3], kl4[2], kl4[3]);
                mma16816(a1, ql[kt][0], ql[kt][1], ql[kt][2], ql[kt][3], kh4[2], kh4[3]);
            }
        }
    };

    s_chunk(AT_BUF0, 0);           // S on keys 0-127
    __syncthreads();               // everyone done reading buf0
    load_kv(0, 1, AT_BUF0);        // V0 -> buf0 (group 3)
    cp_wait<1>();                  // K1 done (V0 may be in flight)
    __syncthreads();
    s_chunk(AT_BUF1, 16);          // S on keys 128-255
    __syncthreads();               // everyone done reading buf1
    load_kv(128, 1, AT_BUF1);      // V1 -> buf1 (group 4)

    // ---- softmax (rows lr and lr+8 of this warp's 16) ----
    const float scale = 0.125f;
    float mx0 = -1e30f, mx1 = -1e30f;
#pragma unroll
    for (int t = 0; t < 32; t++) {
        mx0 = fmaxf(mx0, fmaxf(acc[t][0], acc[t][1]));
        mx1 = fmaxf(mx1, fmaxf(acc[t][2], acc[t][3]));
    }
    mx0 = fmaxf(mx0, __shfl_xor_sync(0xffffffffu, mx0, 1));
    mx0 = fmaxf(mx0, __shfl_xor_sync(0xffffffffu, mx0, 2));
    mx1 = fmaxf(mx1, __shfl_xor_sync(0xffffffffu, mx1, 1));
    mx1 = fmaxf(mx1, __shfl_xor_sync(0xffffffffu, mx1, 2));
    float s0 = 0.f, s1 = 0.f;
#pragma unroll
    for (int t = 0; t < 32; t++) {
        acc[t][0] = __expf((acc[t][0] - mx0) * scale); s0 += acc[t][0];
        acc[t][1] = __expf((acc[t][1] - mx0) * scale); s0 += acc[t][1];
        acc[t][2] = __expf((acc[t][2] - mx1) * scale); s1 += acc[t][2];
        acc[t][3] = __expf((acc[t][3] - mx1) * scale); s1 += acc[t][3];
    }
    s0 += __shfl_xor_sync(0xffffffffu, s0, 1);
    s0 += __shfl_xor_sync(0xffffffffu, s0, 2);
    s1 += __shfl_xor_sync(0xffffffffu, s1, 1);
    s1 += __shfl_xor_sync(0xffffffffu, s1, 2);
    float i0 = 1.f / s0, i1 = 1.f / s1;
#pragma unroll
    for (int t = 0; t < 32; t++) {
        acc[t][0] *= i0; acc[t][1] *= i0; acc[t][2] *= i1; acc[t][3] *= i1;
    }

    // ---- write attn probs (fp32, global, streaming) ----
    {
        float* ar0 = attn + ((size_t)((b * HEADS + h) * NMM) + q0 + wid * 16 + lr) * NSRC + 2 * lc;
        float* ar1 = ar0 + (size_t)8 * NSRC;
#pragma unroll
        for (int t = 0; t < 32; t++) {
            st_cs_f2(ar0 + t * 8, acc[t][0], acc[t][1]);
            st_cs_f2(ar1 + t * 8, acc[t][2], acc[t][3]);
        }
    }

    // ---- convert P to bf16 hi/lo A-fragments ----
    uint32_t ph[16][4], pl[16][4];
#pragma unroll
    for (int t = 0; t < 16; t++) {
        split2(acc[2 * t][0],     acc[2 * t][1],     ph[t][0], pl[t][0]);
        split2(acc[2 * t][2],     acc[2 * t][3],     ph[t][1], pl[t][1]);
        split2(acc[2 * t + 1][0], acc[2 * t + 1][1], ph[t][2], pl[t][2]);
        split2(acc[2 * t + 1][2], acc[2 * t + 1][3], ph[t][3], pl[t][3]);
    }

    // ---- O = P V (3-term split), V B-frags via ldmatrix.x4.trans ----
    float oacc[8][4];
#pragma unroll
    for (int nd = 0; nd < 8; nd++)
#pragma unroll
        for (int v = 0; v < 4; v++) oacc[nd][v] = 0.f;

    auto pv_chunk = [&](uint32_t bufoff, int ktb) {
        uint32_t vbase = smb + (uint32_t)(bufoff + (lane & 15) * QSTR + (lane >> 4) * 8) * 2;
#pragma unroll
        for (int ktl = 0; ktl < 8; ktl++) {
            int kt = ktb + ktl;
            uint32_t vrow = vbase + (uint32_t)(ktl * 16 * QSTR) * 2;
#pragma unroll
            for (int ndp = 0; ndp < 4; ndp++) {
                uint32_t vh4[4], vl4[4];
                ldmx4t(vh4, vrow + ndp * 32);
                ldmx4t(vl4, vrow + (uint32_t)(AT_LOFF * 2) + ndp * 32);
                mma16816(oacc[2 * ndp],     ph[kt][0], ph[kt][1], ph[kt][2], ph[kt][3], vh4[0], vh4[1]);
                mma16816(oacc[2 * ndp],     ph[kt][0], ph[kt][1], ph[kt][2], ph[kt][3], vl4[0], vl4[1]);
                mma16816(oacc[2 * ndp],     pl[kt][0], pl[kt][1], pl[kt][2], pl[kt][3], vh4[0], vh4[1]);
                mma16816(oacc[2 * ndp + 1], ph[kt][0], ph[kt][1], ph[kt][2], ph[kt][3], vh4[2], vh4[3]);
                mma16816(oacc[2 * ndp + 1], ph[kt][0], ph[kt][1], ph[kt][2], ph[kt][3], vl4[2], vl4[3]);
                mma16816(oacc[2 * ndp + 1], pl[kt][0], pl[kt][1], pl[kt][2], pl[kt][3], vh4[2], vh4[3]);
            }
        }
    };

    cp_wait<1>();                  // V0 arrived
    __syncthreads();
    pv_chunk(AT_BUF0, 0);          // keys 0-127
    cp_wait<0>();                  // V1 arrived
    __syncthreads();
    pv_chunk(AT_BUF1, 8);          // keys 128-255

    // ---- write O as bf16 hi/lo ----
    {
        size_t row0 = (size_t)(b * NMM + q0 + wid * 16 + lr);
        __nv_bfloat16* oh0 = Ohi + row0 * DIM + h * HD + 2 * lc;
        __nv_bfloat16* ol0 = Olo + row0 * DIM + h * HD + 2 * lc;
        __nv_bfloat16* oh1 = oh0 + (size_t)8 * DIM;
        __nv_bfloat16* ol1 = ol0 + (size_t)8 * DIM;
#pragma unroll
        for (int nd = 0; nd < 8; nd++) {
            uint32_t hh, ll;
            split2(oacc[nd][0], oacc[nd][1], hh, ll);
            *(uint32_t*)(oh0 + nd * 8) = hh;
            *(uint32_t*)(ol0 + nd * 8) = ll;
            split2(oacc[nd][2], oacc[nd][3], hh, ll);
            *(uint32_t*)(oh1 + nd * 8) = hh;
            *(uint32_t*)(ol1 + nd * 8) = ll;
        }
    }
}

// ---------------------------------------------------------------------------
extern "C" void kernel_launch(void* const* d_in, const int* in_sizes, int n_in,
                              void* d_out, int out_size)
{
    const float* xmm   = (const float*)d_in[0];
    const float* xv    = (const float*)d_in[1];
    const float* xa    = (const float*)d_in[2];
    const float* Wq    = (const float*)d_in[3];
    const float* Wkv   = (const float*)d_in[4];
    const float* Wproj = (const float*)d_in[5];
    const float* bproj = (const float*)d_in[6];

    float* out = (float*)d_out;

    float* attn_fb;
    cudaGetSymbolAddress((void**)&attn_fb, g_attn_fallback);

    __nv_bfloat16 *Axh, *Axl, *Ash, *Asl;
    __nv_bfloat16 *Qh, *Ql, *KVh, *KVl, *Oh, *Ol;
    __nv_bfloat16 *Wqh, *Wql, *Wkh, *Wkl, *Wph, *Wpl;
    cudaGetSymbolAddress((void**)&Axh, g_Axmm_hi);
    cudaGetSymbolAddress((void**)&Axl, g_Axmm_lo);
    cudaGetSymbolAddress((void**)&Ash, g_Asrc_hi);
    cudaGetSymbolAddress((void**)&Asl, g_Asrc_lo);
    cudaGetSymbolAddress((void**)&Qh,  g_Qh);
    cudaGetSymbolAddress((void**)&Ql,  g_Ql);
    cudaGetSymbolAddress((void**)&KVh, g_KVh);
    cudaGetSymbolAddress((void**)&KVl, g_KVl);
    cudaGetSymbolAddress((void**)&Oh,  g_Oh);
    cudaGetSymbolAddress((void**)&Ol,  g_Ol);
    cudaGetSymbolAddress((void**)&Wqh, g_Wqt_hi);
    cudaGetSymbolAddress((void**)&Wql, g_Wqt_lo);
    cudaGetSymbolAddress((void**)&Wkh, g_Wkvt_hi);
    cudaGetSymbolAddress((void**)&Wkl, g_Wkvt_lo);
    cudaGetSymbolAddress((void**)&Wph, g_Wpt_hi);
    cudaGetSymbolAddress((void**)&Wpl, g_Wpt_lo);

    const size_t out_elems  = (size_t)MQ * DIM;
    const size_t attn_elems = (size_t)BS * HEADS * NMM * NSRC;
    float* attn_out = ((size_t)out_size >= out_elems + attn_elems)
                        ? out + out_elems : attn_fb;

    cudaFuncSetAttribute((const void*)gemm_bf16s<true, DIM>,
                         cudaFuncAttributeMaxDynamicSharedMemorySize, GEMM_SMEM);
    cudaFuncSetAttribute((const void*)gemm_bf16s<true, 2 * DIM>,
                         cudaFuncAttributeMaxDynamicSharedMemorySize, GEMM_SMEM);
    cudaFuncSetAttribute((const void*)gemm_bf16s<false, DIM>,
                         cudaFuncAttributeMaxDynamicSharedMemorySize, GEMM_SMEM);
    cudaFuncSetAttribute(attn_mma, cudaFuncAttributeMaxDynamicSharedMemorySize, AT_SMEM_BYTES);

    // --- conversions (merged: 1 transpose launch + 1 split launch) ---
    {
        dim3 bb(32, 8);
        transpose_split_all<<<dim3(2 * DIM / 32, DIM / 32, 3), bb>>>(
            Wq, Wqh, Wql, Wkv, Wkh, Wkl, Wproj, Wph, Wpl);
    }
    split_all_v4<<<dim3(1024, 2), 256>>>((const float4*)xmm,
                                         (const float4*)xv, (const float4*)xa,
                                         (uint2*)Axh, (uint2*)Axl,
                                         (uint2*)Ash, (uint2*)Asl);

    // --- Q = xmm @ Wq  -> bf16 hi/lo ---
    gemm_bf16s<true, DIM><<<dim3(DIM / 128, MQ / 128), 256, GEMM_SMEM>>>(
        Axh, Axl, Wqh, Wql, nullptr, Qh, Ql, nullptr);
    // --- KV = concat(xv,xa) @ Wkv -> bf16 hi/lo ---
    gemm_bf16s<true, 2 * DIM><<<dim3(2 * DIM / 128, MQ / 128), 256, GEMM_SMEM>>>(
        Ash, Asl, Wkh, Wkl, nullptr, KVh, KVl, nullptr);
    // --- attention ---
    attn_mma<<<dim3(NMM / 128, HEADS, BS), 256, AT_SMEM_BYTES>>>(
        Qh, Ql, KVh, KVl, attn_out, Oh, Ol);
    // --- out = O @ Wproj + bproj (fp32) ---
    gemm_bf16s<false, DIM><<<dim3(DIM / 128, MQ / 128), 256, GEMM_SMEM>>>(
        Oh, Ol, Wph, Wpl, out, nullptr, nullptr, bproj);
}